// round 5
// baseline (speedup 1.0000x reference)
#include <cuda_runtime.h>
#include <cstdint>

#define Bm   32
#define Dm   2560
#define Em   5120
#define RK   160
#define STn  16
#define BE   (Bm*Em)
#define BD   (Bm*Dm)
#define KS_IN   20
#define KS_OUT  40
#define KS_DBC  160

typedef unsigned long long ull;

// -------- scratch ----------
__device__ float g_p_ssm[KS_IN * BE];
__device__ float g_p_mlp[KS_IN * BE];
__device__ float g_xt   [BE];
__device__ float g_res  [BE];
__device__ float g_dbcp [KS_DBC * Bm * 192];
__device__ float g_dbc  [Bm * 192];
__device__ float g_z    [BE];
__device__ float g_p_out[KS_OUT * BD];

// -------- f32x2 helpers ----------
__device__ __forceinline__ ull pack2(float x, float y) {
    ull r;
    asm("mov.b64 %0, {%1,%2};" : "=l"(r) : "f"(x), "f"(y));
    return r;
}
__device__ __forceinline__ void fma2(ull& d, ull a, ull b) {
    asm("fma.rn.f32x2 %0, %1, %2, %0;" : "+l"(d) : "l"(a), "l"(b));
}
__device__ __forceinline__ float2 unpack2(ull v) {
    float2 r;
    asm("mov.b64 {%0,%1}, %2;" : "=f"(r.x), "=f"(r.y) : "l"(v));
    return r;
}
__device__ __forceinline__ float silu_f(float v) {
    return v * (1.0f / (1.0f + expf(-v)));
}

// ---------------------------------------------------------------------------
// Core 32-row GEMM body: N-tile 128, 128 threads, micro 4 rows x 8 cols.
// ---------------------------------------------------------------------------
template <int KPER, int NCOLS, int XSTRIDE>
__device__ __forceinline__
void gemm32_body(const float* __restrict__ Xp, const float* __restrict__ W,
                 float* __restrict__ part, int n0, int kbase, int ksIdx) {
    __shared__ ull Xs2[32][34];
    __shared__ ull Ws2[32][64];

    const int t  = threadIdx.x;
    const int cg = t & 15;          // 16 col-groups of 8 cols
    const int rg = t >> 4;          // 8 row-groups of 4 rows
    const int b0 = rg * 4;
    const int qu = cg * 4;

    ull acc[4][4];
#pragma unroll
    for (int j = 0; j < 4; j++)
#pragma unroll
        for (int q = 0; q < 4; q++) acc[j][q] = 0ULL;

    for (int kc = 0; kc < KPER; kc += 32) {
        const int kg = kbase + kc;
#pragma unroll
        for (int i = t; i < 1024; i += 128) {
            int b = i >> 5, kk = i & 31;
            float v = Xp[b * XSTRIDE + kg + kk];
            Xs2[kk][b] = pack2(v, v);
        }
#pragma unroll
        for (int i = t; i < 1024; i += 128) {
            int kk = i >> 5, c4 = i & 31;
            float4 w = *reinterpret_cast<const float4*>(
                &W[(size_t)(kg + kk) * NCOLS + n0 + c4 * 4]);
            ulonglong2 wp;
            wp.x = pack2(w.x, w.y);
            wp.y = pack2(w.z, w.w);
            *reinterpret_cast<ulonglong2*>(&Ws2[kk][c4 * 2]) = wp;
        }
        __syncthreads();
#pragma unroll
        for (int kk = 0; kk < 32; kk++) {
            ulonglong2 w01 = *reinterpret_cast<const ulonglong2*>(&Ws2[kk][qu]);
            ulonglong2 w23 = *reinterpret_cast<const ulonglong2*>(&Ws2[kk][qu + 2]);
            ulonglong2 x01 = *reinterpret_cast<const ulonglong2*>(&Xs2[kk][b0]);
            ulonglong2 x23 = *reinterpret_cast<const ulonglong2*>(&Xs2[kk][b0 + 2]);
            ull xs[4] = {x01.x, x01.y, x23.x, x23.y};
#pragma unroll
            for (int j = 0; j < 4; j++) {
                fma2(acc[j][0], xs[j], w01.x);
                fma2(acc[j][1], xs[j], w01.y);
                fma2(acc[j][2], xs[j], w23.x);
                fma2(acc[j][3], xs[j], w23.y);
            }
        }
        __syncthreads();
    }
#pragma unroll
    for (int j = 0; j < 4; j++) {
        float2 a0 = unpack2(acc[j][0]);
        float2 a1 = unpack2(acc[j][1]);
        float2 a2 = unpack2(acc[j][2]);
        float2 a3 = unpack2(acc[j][3]);
        float* dst = &part[((size_t)ksIdx * Bm + b0 + j) * NCOLS + n0 + cg * 8];
        *reinterpret_cast<float4*>(dst)     = make_float4(a0.x, a0.y, a1.x, a1.y);
        *reinterpret_cast<float4*>(dst + 4) = make_float4(a2.x, a2.y, a3.x, a3.y);
    }
}

// Fused input GEMMs: blockIdx.z = 0 -> ssm, 1 -> mlp. grid(40, KS_IN, 2).
__global__ __launch_bounds__(128)
void gemm_in_kernel(const float* __restrict__ X,
                    const float* __restrict__ W0,
                    const float* __restrict__ W1) {
    const float* W   = (blockIdx.z == 0) ? W0 : W1;
    float* part      = (blockIdx.z == 0) ? g_p_ssm : g_p_mlp;
    constexpr int KPER = Dm / KS_IN;   // 128
    gemm32_body<KPER, Em, Dm>(X, W, part, blockIdx.x * 128,
                              blockIdx.y * KPER, blockIdx.y);
}

// Output GEMM: z(32,5120) @ W_out(5120,2560). grid(20, KS_OUT).
__global__ __launch_bounds__(128)
void gemm_out_kernel(const float* __restrict__ W) {
    constexpr int KPER = Em / KS_OUT;  // 128
    gemm32_body<KPER, Dm, Em>(g_z, W, g_p_out, blockIdx.x * 128,
                              blockIdx.y * KPER, blockIdx.y);
}

// ---------------------------------------------------------------------------
// dbc GEMM: xt(32,5120) @ Wx(5120,192). N-tile 64, 128 threads, micro 4x4.
// grid (3, KS_DBC=160), KPER = 32 (single chunk).
// ---------------------------------------------------------------------------
__global__ __launch_bounds__(128)
void dbc_gemm_kernel(const float* __restrict__ Wx) {
    __shared__ ull Xs2[32][34];
    __shared__ ull Ws2[32][32];

    const int t  = threadIdx.x;
    const int n0 = blockIdx.x * 64;
    const int kg = blockIdx.y * 32;
    const int cg = t & 15;
    const int rg = t >> 4;
    const int b0 = rg * 4;
    const int qu = cg * 2;

    ull acc[4][2];
#pragma unroll
    for (int j = 0; j < 4; j++) { acc[j][0] = 0ULL; acc[j][1] = 0ULL; }

#pragma unroll
    for (int i = t; i < 1024; i += 128) {
        int b = i >> 5, kk = i & 31;
        float v = g_xt[b * Em + kg + kk];
        Xs2[kk][b] = pack2(v, v);
    }
#pragma unroll
    for (int i = t; i < 512; i += 128) {
        int kk = i >> 4, c4 = i & 15;
        float4 w = *reinterpret_cast<const float4*>(
            &Wx[(size_t)(kg + kk) * 192 + n0 + c4 * 4]);
        Ws2[kk][c4 * 2]     = pack2(w.x, w.y);
        Ws2[kk][c4 * 2 + 1] = pack2(w.z, w.w);
    }
    __syncthreads();
#pragma unroll
    for (int kk = 0; kk < 32; kk++) {
        ulonglong2 w = *reinterpret_cast<const ulonglong2*>(&Ws2[kk][qu]);
        ulonglong2 x01 = *reinterpret_cast<const ulonglong2*>(&Xs2[kk][b0]);
        ulonglong2 x23 = *reinterpret_cast<const ulonglong2*>(&Xs2[kk][b0 + 2]);
        ull xs[4] = {x01.x, x01.y, x23.x, x23.y};
#pragma unroll
        for (int j = 0; j < 4; j++) {
            fma2(acc[j][0], xs[j], w.x);
            fma2(acc[j][1], xs[j], w.y);
        }
    }
#pragma unroll
    for (int j = 0; j < 4; j++) {
        float2 a0 = unpack2(acc[j][0]);
        float2 a1 = unpack2(acc[j][1]);
        *reinterpret_cast<float4*>(
            &g_dbcp[((size_t)blockIdx.y * Bm + b0 + j) * 192 + n0 + cg * 4]) =
            make_float4(a0.x, a0.y, a1.x, a1.y);
    }
}

// ---------------------------------------------------------------------------
__global__ __launch_bounds__(256)
void conv_silu_kernel(const float* __restrict__ conv_w,
                      const float* __restrict__ conv_b,
                      const float* __restrict__ conv_states) {
    int idx = blockIdx.x * 256 + threadIdx.x;
    float xssm = 0.0f, xmlp = 0.0f;
#pragma unroll
    for (int ks = 0; ks < KS_IN; ks++) {
        xssm += g_p_ssm[idx + ks * BE];
        xmlp += g_p_mlp[idx + ks * BE];
    }
    float c = conv_b[idx];
    c += conv_states[idx]          * conv_w[idx];
    c += conv_states[idx + BE]     * conv_w[idx + BE];
    c += conv_states[idx + 2 * BE] * conv_w[idx + 2 * BE];
    c += xssm                      * conv_w[idx + 3 * BE];
    g_xt[idx]  = silu_f(c);
    g_res[idx] = silu_f(xmlp);
}

__global__ void dbc_reduce_kernel() {
    int i = blockIdx.x * 256 + threadIdx.x;  // [0, 6144)
    float s = 0.0f;
#pragma unroll 8
    for (int ks = 0; ks < KS_DBC; ks++) s += g_dbcp[ks * Bm * 192 + i];
    g_dbc[i] = s;
}

// ---------------------------------------------------------------------------
__global__ __launch_bounds__(256)
void ssm_kernel(const float* __restrict__ W_dt,
                const float* __restrict__ dt_bias,
                const float* __restrict__ A_log,
                const float* __restrict__ Dv,
                const float* __restrict__ h) {
    int gid = blockIdx.x * 256 + threadIdx.x;  // [0, 16*Em)
    int e  = gid % Em;
    int b0 = (gid / Em) * 2;

    float dt0 = 0.0f, dt1 = 0.0f;
#pragma unroll 8
    for (int k = 0; k < RK; k++) {
        float wd = W_dt[(size_t)k * Em + e];
        dt0 += g_dbc[b0 * 192 + k] * wd;
        dt1 += g_dbc[(b0 + 1) * 192 + k] * wd;
    }

    float bias = dt_bias[e];
    float dval = Dv[e];
    float An[STn];
#pragma unroll
    for (int n = 0; n < STn; n++) An[n] = -expf(A_log[(size_t)e * STn + n]);

    float dts[2] = {dt0, dt1};
#pragma unroll
    for (int j = 0; j < 2; j++) {
        int b = b0 + j;
        float s = dts[j] + bias;
        float dt = (s > 20.0f) ? s : log1pf(expf(s));
        float xt = g_xt[b * Em + e];
        const float* hb = &h[((size_t)b * Em + e) * STn];
        float y = 0.0f;
#pragma unroll
        for (int n = 0; n < STn; n++) {
            float Bv = g_dbc[b * 192 + 160 + n];
            float Cv = g_dbc[b * 192 + 176 + n];
            float dA = expf(dt * An[n]);
            float hn = hb[n] * dA + dt * Bv * xt;
            y += hn * Cv;
        }
        y += dval * xt;
        g_z[b * Em + e] = y * g_res[b * Em + e];
    }
}

__global__ void out_reduce_kernel(float* __restrict__ out) {
    int i = blockIdx.x * 256 + threadIdx.x;  // [0, BD)
    float s = 0.0f;
#pragma unroll 8
    for (int ks = 0; ks < KS_OUT; ks++) s += g_p_out[ks * BD + i];
    out[i] = s;
}

// ---------------------------------------------------------------------------
extern "C" void kernel_launch(void* const* d_in, const int* in_sizes, int n_in,
                              void* d_out, int out_size) {
    const float* x        = (const float*)d_in[0];
    const float* W_in_ssm = (const float*)d_in[1];
    const float* W_in_mlp = (const float*)d_in[2];
    const float* W_out    = (const float*)d_in[3];
    const float* conv_w   = (const float*)d_in[4];
    const float* conv_b   = (const float*)d_in[5];
    const float* conv_st  = (const float*)d_in[6];
    const float* Wx       = (const float*)d_in[7];
    const float* W_dt     = (const float*)d_in[8];
    const float* dt_bias  = (const float*)d_in[9];
    const float* A_log    = (const float*)d_in[10];
    const float* Dvec     = (const float*)d_in[11];
    const float* h        = (const float*)d_in[12];
    float* out = (float*)d_out;

    gemm_in_kernel<<<dim3(40, KS_IN, 2), 128>>>(x, W_in_ssm, W_in_mlp);
    conv_silu_kernel<<<BE / 256, 256>>>(conv_w, conv_b, conv_st);
    dbc_gemm_kernel<<<dim3(3, KS_DBC), 128>>>(Wx);
    dbc_reduce_kernel<<<24, 256>>>();
    ssm_kernel<<<320, 256>>>(W_dt, dt_bias, A_log, Dvec, h);
    gemm_out_kernel<<<dim3(20, KS_OUT), 128>>>(W_out);
    out_reduce_kernel<<<BD / 256, 256>>>(out);
}

// round 6
// speedup vs baseline: 1.4471x; 1.4471x over previous
#include <cuda_runtime.h>
#include <cstdint>

#define Bm   32
#define Dm   2560
#define Em   5120
#define RK   160
#define STn  16
#define BE   (Bm*Em)
#define BD   (Bm*Dm)
#define KS_IN   16
#define KS_OUT  32
#define KS_DBC  40

typedef unsigned long long ull;

// -------- scratch ----------
__device__ float g_p_ssm[KS_IN * BE];
__device__ float g_p_mlp[KS_IN * BE];
__device__ float g_xt   [BE];
__device__ float g_res  [BE];
__device__ float g_dbcp [KS_DBC * Bm * 192];
__device__ float g_dbc  [Bm * 192];
__device__ float g_z    [BE];
__device__ float g_p_out[KS_OUT * BD];

// -------- helpers ----------
__device__ __forceinline__ ull pack2(float x, float y) {
    ull r;
    asm("mov.b64 %0, {%1,%2};" : "=l"(r) : "f"(x), "f"(y));
    return r;
}
__device__ __forceinline__ void fma2(ull& d, ull a, ull b) {
    asm("fma.rn.f32x2 %0, %1, %2, %0;" : "+l"(d) : "l"(a), "l"(b));
}
__device__ __forceinline__ float2 unpack2(ull v) {
    float2 r;
    asm("mov.b64 {%0,%1}, %2;" : "=f"(r.x), "=f"(r.y) : "l"(v));
    return r;
}
__device__ __forceinline__ float silu_f(float v) {
    return v * (1.0f / (1.0f + expf(-v)));
}
__device__ __forceinline__ uint32_t smem_u32(const void* p) {
    uint32_t a;
    asm("{ .reg .u64 t; cvta.to.shared.u64 t, %1; cvt.u32.u64 %0, t; }"
        : "=r"(a) : "l"(p));
    return a;
}
__device__ __forceinline__ void cp_async16(uint32_t dst, const void* src) {
    asm volatile("cp.async.cg.shared.global [%0], [%1], 16;"
                 :: "r"(dst), "l"(src));
}
#define CP_COMMIT()  asm volatile("cp.async.commit_group;")
#define CP_WAIT(n)   asm volatile("cp.async.wait_group %0;" :: "n"(n))

// ---------------------------------------------------------------------------
// Pipelined 32-row GEMM body: N-tile 128, 128 threads, micro 4 rows x 8 cols.
// W: cp.async double-buffered; X: register-prefetched one chunk ahead.
// Dynamic smem: Ws[2][32][64] ull (32768 B) + Xs[2][32][33] ull (16896 B).
// ---------------------------------------------------------------------------
template <int KPER, int NCOLS, int XSTRIDE>
__device__ __forceinline__
void gemm32_pipe(const float* __restrict__ Xp, const float* __restrict__ W,
                 float* __restrict__ part, int n0, int kbase, int ksIdx) {
    extern __shared__ ull sh[];
    ull* Wsb = sh;              // 2 * 2048
    ull* Xsb = sh + 4096;       // 2 * 1056 (32*33)

    const int t  = threadIdx.x;
    const int cg = t & 15;
    const int rg = t >> 4;
    const int b0 = rg * 4;
    const int qu = cg * 4;
    constexpr int NCH = KPER / 32;

    ull acc[4][4];
#pragma unroll
    for (int j = 0; j < 4; j++)
#pragma unroll
        for (int q = 0; q < 4; q++) acc[j][q] = 0ULL;

    float xreg[8];
    // prologue: chunk 0 in flight
    {
        const int kg = kbase;
#pragma unroll
        for (int r = 0; r < 8; r++) {
            int s = t + r * 128, row = s >> 5, c16 = s & 31;
            cp_async16(smem_u32(&Wsb[row * 64 + c16 * 2]),
                       &W[(size_t)(kg + row) * NCOLS + n0 + c16 * 4]);
        }
        CP_COMMIT();
#pragma unroll
        for (int r = 0; r < 8; r++) {
            int i = t + r * 128, b = i >> 5, kk = i & 31;
            xreg[r] = Xp[b * XSTRIDE + kg + kk];
        }
    }

    for (int c = 0; c < NCH; c++) {
        const int p = c & 1;
        ull* Wc = Wsb + p * 2048;
        ull* Xc = Xsb + p * 1056;
        // store X(c) from regs (duplicated lanes)
#pragma unroll
        for (int r = 0; r < 8; r++) {
            int i = t + r * 128, b = i >> 5, kk = i & 31;
            Xc[kk * 33 + b] = pack2(xreg[r], xreg[r]);
        }
        if (c + 1 < NCH) {
            const int kg = kbase + (c + 1) * 32;
            ull* Wn = Wsb + (1 - p) * 2048;
#pragma unroll
            for (int r = 0; r < 8; r++) {
                int s = t + r * 128, row = s >> 5, c16 = s & 31;
                cp_async16(smem_u32(&Wn[row * 64 + c16 * 2]),
                           &W[(size_t)(kg + row) * NCOLS + n0 + c16 * 4]);
            }
            CP_COMMIT();
#pragma unroll
            for (int r = 0; r < 8; r++) {
                int i = t + r * 128, b = i >> 5, kk = i & 31;
                xreg[r] = Xp[b * XSTRIDE + kg + kk];
            }
            CP_WAIT(1);
        } else {
            CP_WAIT(0);
        }
        __syncthreads();
#pragma unroll
        for (int kk = 0; kk < 32; kk++) {
            ulonglong2 w01 = *reinterpret_cast<const ulonglong2*>(&Wc[kk * 64 + qu]);
            ulonglong2 w23 = *reinterpret_cast<const ulonglong2*>(&Wc[kk * 64 + qu + 2]);
            ull x0 = Xc[kk * 33 + b0];
            ull x1 = Xc[kk * 33 + b0 + 1];
            ull x2 = Xc[kk * 33 + b0 + 2];
            ull x3 = Xc[kk * 33 + b0 + 3];
            ull xs[4] = {x0, x1, x2, x3};
#pragma unroll
            for (int j = 0; j < 4; j++) {
                fma2(acc[j][0], xs[j], w01.x);
                fma2(acc[j][1], xs[j], w01.y);
                fma2(acc[j][2], xs[j], w23.x);
                fma2(acc[j][3], xs[j], w23.y);
            }
        }
        __syncthreads();
    }
#pragma unroll
    for (int j = 0; j < 4; j++) {
        float2 a0 = unpack2(acc[j][0]);
        float2 a1 = unpack2(acc[j][1]);
        float2 a2 = unpack2(acc[j][2]);
        float2 a3 = unpack2(acc[j][3]);
        float* dst = &part[((size_t)ksIdx * Bm + b0 + j) * NCOLS + n0 + cg * 8];
        *reinterpret_cast<float4*>(dst)     = make_float4(a0.x, a0.y, a1.x, a1.y);
        *reinterpret_cast<float4*>(dst + 4) = make_float4(a2.x, a2.y, a3.x, a3.y);
    }
}

__global__ __launch_bounds__(128)
void gemm_ssm_kernel(const float* __restrict__ X, const float* __restrict__ W) {
    constexpr int KPER = Dm / KS_IN;  // 160
    gemm32_pipe<KPER, Em, Dm>(X, W, g_p_ssm, blockIdx.x * 128,
                              blockIdx.y * KPER, blockIdx.y);
}
__global__ __launch_bounds__(128)
void gemm_mlp_kernel(const float* __restrict__ X, const float* __restrict__ W) {
    constexpr int KPER = Dm / KS_IN;  // 160
    gemm32_pipe<KPER, Em, Dm>(X, W, g_p_mlp, blockIdx.x * 128,
                              blockIdx.y * KPER, blockIdx.y);
}
__global__ __launch_bounds__(128)
void gemm_out_kernel(const float* __restrict__ W) {
    constexpr int KPER = Em / KS_OUT;  // 160
    gemm32_pipe<KPER, Dm, Em>(g_z, W, g_p_out, blockIdx.x * 128,
                              blockIdx.y * KPER, blockIdx.y);
}

// ---------------------------------------------------------------------------
// dbc GEMM: xt(32,5120) @ Wx(5120,192), pipelined. N-tile 64, 128 threads.
// grid (3, KS_DBC=40), KPER = 128 -> 4 chunks of 32.
// ---------------------------------------------------------------------------
__global__ __launch_bounds__(128)
void dbc_gemm_kernel(const float* __restrict__ Wx) {
    __shared__ ull Wsb[2][32][32];   // 16 KB
    __shared__ ull Xsb[2][32][33];   // 16.9 KB

    const int t  = threadIdx.x;
    const int n0 = blockIdx.x * 64;
    constexpr int KPER = Em / KS_DBC;  // 128
    constexpr int NCH  = KPER / 32;    // 4
    const int kbase = blockIdx.y * KPER;
    const int cg = t & 15;
    const int rg = t >> 4;
    const int b0 = rg * 4;
    const int qu = cg * 2;

    ull acc[4][2];
#pragma unroll
    for (int j = 0; j < 4; j++) { acc[j][0] = 0ULL; acc[j][1] = 0ULL; }

    float xreg[8];
    {
        const int kg = kbase;
#pragma unroll
        for (int r = 0; r < 4; r++) {       // 32 rows * 16 segs = 512
            int s = t + r * 128, row = s >> 4, c16 = s & 15;
            cp_async16(smem_u32(&Wsb[0][row][c16 * 2]),
                       &Wx[(size_t)(kg + row) * 192 + n0 + c16 * 4]);
        }
        CP_COMMIT();
#pragma unroll
        for (int r = 0; r < 8; r++) {
            int i = t + r * 128, b = i >> 5, kk = i & 31;
            xreg[r] = g_xt[b * Em + kg + kk];
        }
    }

    for (int c = 0; c < NCH; c++) {
        const int p = c & 1;
#pragma unroll
        for (int r = 0; r < 8; r++) {
            int i = t + r * 128, b = i >> 5, kk = i & 31;
            Xsb[p][kk][b] = pack2(xreg[r], xreg[r]);
        }
        if (c + 1 < NCH) {
            const int kg = kbase + (c + 1) * 32;
#pragma unroll
            for (int r = 0; r < 4; r++) {
                int s = t + r * 128, row = s >> 4, c16 = s & 15;
                cp_async16(smem_u32(&Wsb[1 - p][row][c16 * 2]),
                           &Wx[(size_t)(kg + row) * 192 + n0 + c16 * 4]);
            }
            CP_COMMIT();
#pragma unroll
            for (int r = 0; r < 8; r++) {
                int i = t + r * 128, b = i >> 5, kk = i & 31;
                xreg[r] = g_xt[b * Em + kg + kk];
            }
            CP_WAIT(1);
        } else {
            CP_WAIT(0);
        }
        __syncthreads();
#pragma unroll
        for (int kk = 0; kk < 32; kk++) {
            ulonglong2 w = *reinterpret_cast<const ulonglong2*>(&Wsb[p][kk][qu]);
            ull xs[4] = {Xsb[p][kk][b0], Xsb[p][kk][b0 + 1],
                         Xsb[p][kk][b0 + 2], Xsb[p][kk][b0 + 3]};
#pragma unroll
            for (int j = 0; j < 4; j++) {
                fma2(acc[j][0], xs[j], w.x);
                fma2(acc[j][1], xs[j], w.y);
            }
        }
        __syncthreads();
    }
#pragma unroll
    for (int j = 0; j < 4; j++) {
        float2 a0 = unpack2(acc[j][0]);
        float2 a1 = unpack2(acc[j][1]);
        *reinterpret_cast<float4*>(
            &g_dbcp[((size_t)blockIdx.y * Bm + b0 + j) * 192 + n0 + cg * 4]) =
            make_float4(a0.x, a0.y, a1.x, a1.y);
    }
}

// ---------------------------------------------------------------------------
__global__ __launch_bounds__(256)
void conv_silu_kernel(const float* __restrict__ conv_w,
                      const float* __restrict__ conv_b,
                      const float* __restrict__ conv_states) {
    int idx = blockIdx.x * 256 + threadIdx.x;
    float xssm = 0.0f, xmlp = 0.0f;
#pragma unroll
    for (int ks = 0; ks < KS_IN; ks++) {
        xssm += g_p_ssm[idx + ks * BE];
        xmlp += g_p_mlp[idx + ks * BE];
    }
    float c = conv_b[idx];
    c += conv_states[idx]          * conv_w[idx];
    c += conv_states[idx + BE]     * conv_w[idx + BE];
    c += conv_states[idx + 2 * BE] * conv_w[idx + 2 * BE];
    c += xssm                      * conv_w[idx + 3 * BE];
    g_xt[idx]  = silu_f(c);
    g_res[idx] = silu_f(xmlp);
}

__global__ void dbc_reduce_kernel() {
    int i = blockIdx.x * 256 + threadIdx.x;  // [0, 6144)
    float s = 0.0f;
#pragma unroll 8
    for (int ks = 0; ks < KS_DBC; ks++) s += g_dbcp[ks * Bm * 192 + i];
    g_dbc[i] = s;
}

// ---------------------------------------------------------------------------
__global__ __launch_bounds__(256)
void ssm_kernel(const float* __restrict__ W_dt,
                const float* __restrict__ dt_bias,
                const float* __restrict__ A_log,
                const float* __restrict__ Dv,
                const float* __restrict__ h) {
    int gid = blockIdx.x * 256 + threadIdx.x;  // [0, 16*Em)
    int e  = gid % Em;
    int b0 = (gid / Em) * 2;

    float dt0 = 0.0f, dt1 = 0.0f;
#pragma unroll 8
    for (int k = 0; k < RK; k++) {
        float wd = W_dt[(size_t)k * Em + e];
        dt0 += g_dbc[b0 * 192 + k] * wd;
        dt1 += g_dbc[(b0 + 1) * 192 + k] * wd;
    }

    float bias = dt_bias[e];
    float dval = Dv[e];
    float An[STn];
#pragma unroll
    for (int n = 0; n < STn; n++) An[n] = -expf(A_log[(size_t)e * STn + n]);

    float dts[2] = {dt0, dt1};
#pragma unroll
    for (int j = 0; j < 2; j++) {
        int b = b0 + j;
        float s = dts[j] + bias;
        float dt = (s > 20.0f) ? s : log1pf(expf(s));
        float xt = g_xt[b * Em + e];
        const float* hb = &h[((size_t)b * Em + e) * STn];
        float y = 0.0f;
#pragma unroll
        for (int n = 0; n < STn; n++) {
            float Bv = g_dbc[b * 192 + 160 + n];
            float Cv = g_dbc[b * 192 + 176 + n];
            float dA = expf(dt * An[n]);
            float hn = hb[n] * dA + dt * Bv * xt;
            y += hn * Cv;
        }
        y += dval * xt;
        g_z[b * Em + e] = y * g_res[b * Em + e];
    }
}

__global__ void out_reduce_kernel(float* __restrict__ out) {
    int i = blockIdx.x * 256 + threadIdx.x;  // [0, BD)
    float s = 0.0f;
#pragma unroll 8
    for (int ks = 0; ks < KS_OUT; ks++) s += g_p_out[ks * BD + i];
    out[i] = s;
}

// ---------------------------------------------------------------------------
extern "C" void kernel_launch(void* const* d_in, const int* in_sizes, int n_in,
                              void* d_out, int out_size) {
    const float* x        = (const float*)d_in[0];
    const float* W_in_ssm = (const float*)d_in[1];
    const float* W_in_mlp = (const float*)d_in[2];
    const float* W_out    = (const float*)d_in[3];
    const float* conv_w   = (const float*)d_in[4];
    const float* conv_b   = (const float*)d_in[5];
    const float* conv_st  = (const float*)d_in[6];
    const float* Wx       = (const float*)d_in[7];
    const float* W_dt     = (const float*)d_in[8];
    const float* dt_bias  = (const float*)d_in[9];
    const float* A_log    = (const float*)d_in[10];
    const float* Dvec     = (const float*)d_in[11];
    const float* h        = (const float*)d_in[12];
    float* out = (float*)d_out;

    // dynamic smem: 4096 ull (W dbl) + 2112 ull (X dbl) = 49664 bytes
    const int DSMEM = (4096 + 2 * 1056) * 8;
    static bool attr_set = false;
    if (!attr_set) {
        cudaFuncSetAttribute(gemm_ssm_kernel,
                             cudaFuncAttributeMaxDynamicSharedMemorySize, DSMEM);
        cudaFuncSetAttribute(gemm_mlp_kernel,
                             cudaFuncAttributeMaxDynamicSharedMemorySize, DSMEM);
        cudaFuncSetAttribute(gemm_out_kernel,
                             cudaFuncAttributeMaxDynamicSharedMemorySize, DSMEM);
        attr_set = true;
    }

    gemm_ssm_kernel<<<dim3(40, KS_IN), 128, DSMEM>>>(x, W_in_ssm);
    gemm_mlp_kernel<<<dim3(40, KS_IN), 128, DSMEM>>>(x, W_in_mlp);
    conv_silu_kernel<<<BE / 256, 256>>>(conv_w, conv_b, conv_st);
    dbc_gemm_kernel<<<dim3(3, KS_DBC), 128>>>(Wx);
    dbc_reduce_kernel<<<24, 256>>>();
    ssm_kernel<<<320, 256>>>(W_dt, dt_bias, A_log, Dvec, h);
    gemm_out_kernel<<<dim3(20, KS_OUT), 128, DSMEM>>>(W_out);
    out_reduce_kernel<<<BD / 256, 256>>>(out);
}

// round 7
// speedup vs baseline: 2.2068x; 1.5249x over previous
#include <cuda_runtime.h>
#include <cuda_bf16.h>
#include <cstdint>

#define Bm   32
#define Dm   2560
#define Em   5120
#define RK   160
#define STn  16
#define BE   (Bm*Em)
#define BD   (Bm*Dm)
#define KS_IN   16
#define KS_OUT  32
#define KS_DBC  40

typedef unsigned long long ull;

// -------- scratch ----------
__device__ float g_p_ssm[KS_IN * BE];
__device__ float g_p_mlp[KS_IN * BE];
__device__ float g_xt   [BE];
__device__ float g_res  [BE];
__device__ float g_dbcp [KS_DBC * Bm * 192];
__device__ float g_dbc  [Bm * 192];
__device__ float g_z    [BE];
__device__ float g_p_out[KS_OUT * BD];

// -------- helpers ----------
__device__ __forceinline__ ull pack2(float x, float y) {
    ull r;
    asm("mov.b64 %0, {%1,%2};" : "=l"(r) : "f"(x), "f"(y));
    return r;
}
__device__ __forceinline__ void fma2(ull& d, ull a, ull b) {
    asm("fma.rn.f32x2 %0, %1, %2, %0;" : "+l"(d) : "l"(a), "l"(b));
}
__device__ __forceinline__ float2 unpack2(ull v) {
    float2 r;
    asm("mov.b64 {%0,%1}, %2;" : "=f"(r.x), "=f"(r.y) : "l"(v));
    return r;
}
__device__ __forceinline__ float silu_f(float v) {
    return v * (1.0f / (1.0f + expf(-v)));
}
__device__ __forceinline__ uint32_t smem_u32(const void* p) {
    uint32_t a;
    asm("{ .reg .u64 t; cvta.to.shared.u64 t, %1; cvt.u32.u64 %0, t; }"
        : "=r"(a) : "l"(p));
    return a;
}
__device__ __forceinline__ void cp_async16(uint32_t dst, const void* src) {
    asm volatile("cp.async.cg.shared.global [%0], [%1], 16;"
                 :: "r"(dst), "l"(src));
}
#define CP_COMMIT()  asm volatile("cp.async.commit_group;")
#define CP_WAIT(n)   asm volatile("cp.async.wait_group %0;" :: "n"(n))

__device__ __forceinline__ void ldsm_x4(uint32_t* r, uint32_t addr) {
    asm volatile("ldmatrix.sync.aligned.m8n8.x4.shared.b16 {%0,%1,%2,%3}, [%4];"
                 : "=r"(r[0]), "=r"(r[1]), "=r"(r[2]), "=r"(r[3]) : "r"(addr));
}
__device__ __forceinline__ void ldsm_x4t(uint32_t* r, uint32_t addr) {
    asm volatile("ldmatrix.sync.aligned.m8n8.x4.trans.shared.b16 {%0,%1,%2,%3}, [%4];"
                 : "=r"(r[0]), "=r"(r[1]), "=r"(r[2]), "=r"(r[3]) : "r"(addr));
}
__device__ __forceinline__ void mma_bf16(float* d, const uint32_t* a,
                                         const uint32_t* b) {
    asm volatile(
        "mma.sync.aligned.m16n8k16.row.col.f32.bf16.bf16.f32 "
        "{%0,%1,%2,%3}, {%4,%5,%6,%7}, {%8,%9}, {%0,%1,%2,%3};"
        : "+f"(d[0]), "+f"(d[1]), "+f"(d[2]), "+f"(d[3])
        : "r"(a[0]), "r"(a[1]), "r"(a[2]), "r"(a[3]), "r"(b[0]), "r"(b[1]));
}

// ---------------------------------------------------------------------------
// Tensor-core 32-row GEMM body: N-tile 128, 128 threads (4 warps).
// W fp32 streamed via cp.async double buffer, converted in smem to bf16 hi/lo.
// D = Xh*Wh + Xh*Wl + Xl*Wh with fp32 accumulation (mma.m16n8k16).
// ---------------------------------------------------------------------------
template <int KPER, int NCOLS, int XSTRIDE>
__device__ __forceinline__
void gemm32_tc(const float* __restrict__ Xp, const float* __restrict__ W,
               float* __restrict__ part, int n0, int kbase, int ksIdx) {
    __shared__ __align__(16) float          Wfs[2][16][128];  // 16 KB
    __shared__ __align__(16) __nv_bfloat16  Whs[16][136];
    __shared__ __align__(16) __nv_bfloat16  Wls[16][136];
    __shared__ __align__(16) __nv_bfloat16  Xhs[32][24];
    __shared__ __align__(16) __nv_bfloat16  Xls[32][24];

    const int t    = threadIdx.x;
    const int lane = t & 31;
    const int warp = t >> 5;
    constexpr int NCH = KPER / 16;

    float d[2][4][4];
#pragma unroll
    for (int m = 0; m < 2; m++)
#pragma unroll
        for (int s = 0; s < 4; s++)
#pragma unroll
            for (int q = 0; q < 4; q++) d[m][s][q] = 0.0f;

    float xreg[4];
    // prologue: chunk 0 in flight
    {
        const int kg = kbase;
#pragma unroll
        for (int r = 0; r < 4; r++) {
            int s = t + r * 128, k = s >> 5, seg = s & 31;
            cp_async16(smem_u32(&Wfs[0][k][seg * 4]),
                       &W[(size_t)(kg + k) * NCOLS + n0 + seg * 4]);
        }
        CP_COMMIT();
#pragma unroll
        for (int r = 0; r < 4; r++) {
            int i = t + r * 128, m = i >> 4, k = i & 15;
            xreg[r] = Xp[m * XSTRIDE + kg + k];
        }
    }

    // ldmatrix lane addresses
    const int amr = ((lane >> 3) & 1) * 8 + (lane & 7);
    const int akh = (lane >> 4) * 8;
    const uint32_t aXh0 = smem_u32(&Xhs[amr][akh]);
    const uint32_t aXh1 = smem_u32(&Xhs[16 + amr][akh]);
    const uint32_t aXl0 = smem_u32(&Xls[amr][akh]);
    const uint32_t aXl1 = smem_u32(&Xls[16 + amr][akh]);
    const int bk  = ((lane >> 3) & 1) * 8 + (lane & 7);
    const int bno = ((lane >> 4) & 1) * 8;

    for (int c = 0; c < NCH; c++) {
        const int p = c & 1;
        if (c + 1 < NCH) {
            const int kg = kbase + (c + 1) * 16;
#pragma unroll
            for (int r = 0; r < 4; r++) {
                int s = t + r * 128, k = s >> 5, seg = s & 31;
                cp_async16(smem_u32(&Wfs[1 - p][k][seg * 4]),
                           &W[(size_t)(kg + k) * NCOLS + n0 + seg * 4]);
            }
            CP_COMMIT();
            CP_WAIT(1);
        } else {
            CP_WAIT(0);
        }
        __syncthreads();   // Wfs[p] visible; all warps done with prev mma

        // convert W chunk: thread t owns column n=t
#pragma unroll
        for (int k = 0; k < 16; k++) {
            float v = Wfs[p][k][t];
            __nv_bfloat16 hi = __float2bfloat16(v);
            Whs[k][t] = hi;
            Wls[k][t] = __float2bfloat16(v - __bfloat162float(hi));
        }
        // convert X chunk from prefetch regs
#pragma unroll
        for (int r = 0; r < 4; r++) {
            int i = t + r * 128, m = i >> 4, k = i & 15;
            float v = xreg[r];
            __nv_bfloat16 hi = __float2bfloat16(v);
            Xhs[m][k] = hi;
            Xls[m][k] = __float2bfloat16(v - __bfloat162float(hi));
        }
        if (c + 1 < NCH) {
            const int kg = kbase + (c + 1) * 16;
#pragma unroll
            for (int r = 0; r < 4; r++) {
                int i = t + r * 128, m = i >> 4, k = i & 15;
                xreg[r] = Xp[m * XSTRIDE + kg + k];
            }
        }
        __syncthreads();   // bf16 tiles ready

        uint32_t ah0[4], ah1[4], al0[4], al1[4];
        ldsm_x4(ah0, aXh0);
        ldsm_x4(ah1, aXh1);
        ldsm_x4(al0, aXl0);
        ldsm_x4(al1, aXl1);
#pragma unroll
        for (int s = 0; s < 2; s++) {       // pairs of n8 tiles
            const int nb = warp * 32 + s * 16;
            uint32_t bh[4], bl[4];
            ldsm_x4t(bh, smem_u32(&Whs[bk][nb + bno]));
            ldsm_x4t(bl, smem_u32(&Wls[bk][nb + bno]));
#pragma unroll
            for (int j = 0; j < 2; j++) {
                float* d0 = d[0][s * 2 + j];
                float* d1 = d[1][s * 2 + j];
                mma_bf16(d0, ah0, &bh[j * 2]);
                mma_bf16(d0, ah0, &bl[j * 2]);
                mma_bf16(d0, al0, &bh[j * 2]);
                mma_bf16(d1, ah1, &bh[j * 2]);
                mma_bf16(d1, ah1, &bl[j * 2]);
                mma_bf16(d1, al1, &bh[j * 2]);
            }
        }
    }

    // epilogue
    const int g = lane >> 2, q = lane & 3;
#pragma unroll
    for (int mt = 0; mt < 2; mt++) {
#pragma unroll
        for (int s = 0; s < 4; s++) {
            int col = n0 + warp * 32 + s * 8 + q * 2;
            size_t r0 = (size_t)(ksIdx * Bm + mt * 16 + g) * NCOLS + col;
            size_t r1 = (size_t)(ksIdx * Bm + mt * 16 + g + 8) * NCOLS + col;
            *reinterpret_cast<float2*>(&part[r0]) =
                make_float2(d[mt][s][0], d[mt][s][1]);
            *reinterpret_cast<float2*>(&part[r1]) =
                make_float2(d[mt][s][2], d[mt][s][3]);
        }
    }
}

__global__ __launch_bounds__(128)
void gemm_ssm_kernel(const float* __restrict__ X, const float* __restrict__ W) {
    constexpr int KPER = Dm / KS_IN;  // 160
    gemm32_tc<KPER, Em, Dm>(X, W, g_p_ssm, blockIdx.x * 128,
                            blockIdx.y * KPER, blockIdx.y);
}
__global__ __launch_bounds__(128)
void gemm_mlp_kernel(const float* __restrict__ X, const float* __restrict__ W) {
    constexpr int KPER = Dm / KS_IN;  // 160
    gemm32_tc<KPER, Em, Dm>(X, W, g_p_mlp, blockIdx.x * 128,
                            blockIdx.y * KPER, blockIdx.y);
}
__global__ __launch_bounds__(128)
void gemm_out_kernel(const float* __restrict__ W) {
    constexpr int KPER = Em / KS_OUT;  // 160
    gemm32_tc<KPER, Dm, Em>(g_z, W, g_p_out, blockIdx.x * 128,
                            blockIdx.y * KPER, blockIdx.y);
}

// ---------------------------------------------------------------------------
// dbc GEMM (unchanged from R6): xt(32,5120) @ Wx(5120,192), f32x2 pipelined.
// ---------------------------------------------------------------------------
__global__ __launch_bounds__(128)
void dbc_gemm_kernel(const float* __restrict__ Wx) {
    __shared__ ull Wsb[2][32][32];
    __shared__ ull Xsb[2][32][33];

    const int t  = threadIdx.x;
    const int n0 = blockIdx.x * 64;
    constexpr int KPER = Em / KS_DBC;  // 128
    constexpr int NCH  = KPER / 32;    // 4
    const int kbase = blockIdx.y * KPER;
    const int cg = t & 15;
    const int rg = t >> 4;
    const int b0 = rg * 4;
    const int qu = cg * 2;

    ull acc[4][2];
#pragma unroll
    for (int j = 0; j < 4; j++) { acc[j][0] = 0ULL; acc[j][1] = 0ULL; }

    float xreg[8];
    {
        const int kg = kbase;
#pragma unroll
        for (int r = 0; r < 4; r++) {
            int s = t + r * 128, row = s >> 4, c16 = s & 15;
            cp_async16(smem_u32(&Wsb[0][row][c16 * 2]),
                       &Wx[(size_t)(kg + row) * 192 + n0 + c16 * 4]);
        }
        CP_COMMIT();
#pragma unroll
        for (int r = 0; r < 8; r++) {
            int i = t + r * 128, b = i >> 5, kk = i & 31;
            xreg[r] = g_xt[b * Em + kg + kk];
        }
    }

    for (int c = 0; c < NCH; c++) {
        const int p = c & 1;
#pragma unroll
        for (int r = 0; r < 8; r++) {
            int i = t + r * 128, b = i >> 5, kk = i & 31;
            Xsb[p][kk][b] = pack2(xreg[r], xreg[r]);
        }
        if (c + 1 < NCH) {
            const int kg = kbase + (c + 1) * 32;
#pragma unroll
            for (int r = 0; r < 4; r++) {
                int s = t + r * 128, row = s >> 4, c16 = s & 15;
                cp_async16(smem_u32(&Wsb[1 - p][row][c16 * 2]),
                           &Wx[(size_t)(kg + row) * 192 + n0 + c16 * 4]);
            }
            CP_COMMIT();
#pragma unroll
            for (int r = 0; r < 8; r++) {
                int i = t + r * 128, b = i >> 5, kk = i & 31;
                xreg[r] = g_xt[b * Em + kg + kk];
            }
            CP_WAIT(1);
        } else {
            CP_WAIT(0);
        }
        __syncthreads();
#pragma unroll
        for (int kk = 0; kk < 32; kk++) {
            ulonglong2 w = *reinterpret_cast<const ulonglong2*>(&Wsb[p][kk][qu]);
            ull xs[4] = {Xsb[p][kk][b0], Xsb[p][kk][b0 + 1],
                         Xsb[p][kk][b0 + 2], Xsb[p][kk][b0 + 3]};
#pragma unroll
            for (int j = 0; j < 4; j++) {
                fma2(acc[j][0], xs[j], w.x);
                fma2(acc[j][1], xs[j], w.y);
            }
        }
        __syncthreads();
    }
#pragma unroll
    for (int j = 0; j < 4; j++) {
        float2 a0 = unpack2(acc[j][0]);
        float2 a1 = unpack2(acc[j][1]);
        *reinterpret_cast<float4*>(
            &g_dbcp[((size_t)blockIdx.y * Bm + b0 + j) * 192 + n0 + cg * 4]) =
            make_float4(a0.x, a0.y, a1.x, a1.y);
    }
}

// ---------------------------------------------------------------------------
__global__ __launch_bounds__(256)
void conv_silu_kernel(const float* __restrict__ conv_w,
                      const float* __restrict__ conv_b,
                      const float* __restrict__ conv_states) {
    int idx = blockIdx.x * 256 + threadIdx.x;
    float xssm = 0.0f, xmlp = 0.0f;
#pragma unroll
    for (int ks = 0; ks < KS_IN; ks++) {
        xssm += g_p_ssm[idx + ks * BE];
        xmlp += g_p_mlp[idx + ks * BE];
    }
    float c = conv_b[idx];
    c += conv_states[idx]          * conv_w[idx];
    c += conv_states[idx + BE]     * conv_w[idx + BE];
    c += conv_states[idx + 2 * BE] * conv_w[idx + 2 * BE];
    c += xssm                      * conv_w[idx + 3 * BE];
    g_xt[idx]  = silu_f(c);
    g_res[idx] = silu_f(xmlp);
}

__global__ void dbc_reduce_kernel() {
    int i = blockIdx.x * 256 + threadIdx.x;  // [0, 6144)
    float s = 0.0f;
#pragma unroll 8
    for (int ks = 0; ks < KS_DBC; ks++) s += g_dbcp[ks * Bm * 192 + i];
    g_dbc[i] = s;
}

// ---------------------------------------------------------------------------
__global__ __launch_bounds__(256)
void ssm_kernel(const float* __restrict__ W_dt,
                const float* __restrict__ dt_bias,
                const float* __restrict__ A_log,
                const float* __restrict__ Dv,
                const float* __restrict__ h) {
    int gid = blockIdx.x * 256 + threadIdx.x;  // [0, 16*Em)
    int e  = gid % Em;
    int b0 = (gid / Em) * 2;

    float dt0 = 0.0f, dt1 = 0.0f;
#pragma unroll 8
    for (int k = 0; k < RK; k++) {
        float wd = W_dt[(size_t)k * Em + e];
        dt0 += g_dbc[b0 * 192 + k] * wd;
        dt1 += g_dbc[(b0 + 1) * 192 + k] * wd;
    }

    float bias = dt_bias[e];
    float dval = Dv[e];
    float An[STn];
#pragma unroll
    for (int n = 0; n < STn; n++) An[n] = -expf(A_log[(size_t)e * STn + n]);

    float dts[2] = {dt0, dt1};
#pragma unroll
    for (int j = 0; j < 2; j++) {
        int b = b0 + j;
        float s = dts[j] + bias;
        float dt = (s > 20.0f) ? s : log1pf(expf(s));
        float xt = g_xt[b * Em + e];
        const float* hb = &h[((size_t)b * Em + e) * STn];
        float y = 0.0f;
#pragma unroll
        for (int n = 0; n < STn; n++) {
            float Bv = g_dbc[b * 192 + 160 + n];
            float Cv = g_dbc[b * 192 + 176 + n];
            float dA = expf(dt * An[n]);
            float hn = hb[n] * dA + dt * Bv * xt;
            y += hn * Cv;
        }
        y += dval * xt;
        g_z[b * Em + e] = y * g_res[b * Em + e];
    }
}

__global__ void out_reduce_kernel(float* __restrict__ out) {
    int i = blockIdx.x * 256 + threadIdx.x;  // [0, BD)
    float s = 0.0f;
#pragma unroll 8
    for (int ks = 0; ks < KS_OUT; ks++) s += g_p_out[ks * BD + i];
    out[i] = s;
}

// ---------------------------------------------------------------------------
extern "C" void kernel_launch(void* const* d_in, const int* in_sizes, int n_in,
                              void* d_out, int out_size) {
    const float* x        = (const float*)d_in[0];
    const float* W_in_ssm = (const float*)d_in[1];
    const float* W_in_mlp = (const float*)d_in[2];
    const float* W_out    = (const float*)d_in[3];
    const float* conv_w   = (const float*)d_in[4];
    const float* conv_b   = (const float*)d_in[5];
    const float* conv_st  = (const float*)d_in[6];
    const float* Wx       = (const float*)d_in[7];
    const float* W_dt     = (const float*)d_in[8];
    const float* dt_bias  = (const float*)d_in[9];
    const float* A_log    = (const float*)d_in[10];
    const float* Dvec     = (const float*)d_in[11];
    const float* h        = (const float*)d_in[12];
    float* out = (float*)d_out;

    gemm_ssm_kernel<<<dim3(40, KS_IN), 128>>>(x, W_in_ssm);
    gemm_mlp_kernel<<<dim3(40, KS_IN), 128>>>(x, W_in_mlp);
    conv_silu_kernel<<<BE / 256, 256>>>(conv_w, conv_b, conv_st);
    dbc_gemm_kernel<<<dim3(3, KS_DBC), 128>>>(Wx);
    dbc_reduce_kernel<<<24, 256>>>();
    ssm_kernel<<<320, 256>>>(W_dt, dt_bias, A_log, Dvec, h);
    gemm_out_kernel<<<dim3(20, KS_OUT), 128>>>(W_out);
    out_reduce_kernel<<<BD / 256, 256>>>(out);
}

// round 8
// speedup vs baseline: 2.5621x; 1.1610x over previous
#include <cuda_runtime.h>
#include <cuda_bf16.h>
#include <cstdint>

#define Bm   32
#define Dm   2560
#define Em   5120
#define RK   160
#define STn  16
#define BE   (Bm*Em)
#define BD   (Bm*Dm)
#define KS_IN   16
#define KS_OUT  32
#define KS_DBC  40

typedef unsigned long long ull;

// -------- scratch ----------
__device__ float g_p_ssm[KS_IN * BE];
__device__ float g_p_mlp[KS_IN * BE];
__device__ float g_xt   [BE];
__device__ float g_res  [BE];
__device__ float g_dbcp [KS_DBC * Bm * 192];
__device__ float g_dbc  [Bm * 192];
__device__ float g_z    [BE];
__device__ float g_p_out[KS_OUT * BD];

// -------- helpers ----------
__device__ __forceinline__ ull pack2(float x, float y) {
    ull r;
    asm("mov.b64 %0, {%1,%2};" : "=l"(r) : "f"(x), "f"(y));
    return r;
}
__device__ __forceinline__ void fma2(ull& d, ull a, ull b) {
    asm("fma.rn.f32x2 %0, %1, %2, %0;" : "+l"(d) : "l"(a), "l"(b));
}
__device__ __forceinline__ float2 unpack2(ull v) {
    float2 r;
    asm("mov.b64 {%0,%1}, %2;" : "=f"(r.x), "=f"(r.y) : "l"(v));
    return r;
}
__device__ __forceinline__ float silu_f(float v) {
    return v * (1.0f / (1.0f + expf(-v)));
}
__device__ __forceinline__ uint32_t smem_u32(const void* p) {
    uint32_t a;
    asm("{ .reg .u64 t; cvta.to.shared.u64 t, %1; cvt.u32.u64 %0, t; }"
        : "=r"(a) : "l"(p));
    return a;
}
__device__ __forceinline__ void cp_async16(uint32_t dst, const void* src) {
    asm volatile("cp.async.cg.shared.global [%0], [%1], 16;"
                 :: "r"(dst), "l"(src));
}
#define CP_COMMIT()  asm volatile("cp.async.commit_group;")
#define CP_WAIT(n)   asm volatile("cp.async.wait_group %0;" :: "n"(n))

__device__ __forceinline__ uint32_t f2tf(float v) {
    uint32_t u;
    asm("cvt.rna.tf32.f32 %0, %1;" : "=r"(u) : "f"(v));
    return u;
}
__device__ __forceinline__ void mma_tf32(float* d, const uint32_t* a,
                                         uint32_t b0, uint32_t b1) {
    asm volatile(
        "mma.sync.aligned.m16n8k8.row.col.f32.tf32.tf32.f32 "
        "{%0,%1,%2,%3}, {%4,%5,%6,%7}, {%8,%9}, {%0,%1,%2,%3};"
        : "+f"(d[0]), "+f"(d[1]), "+f"(d[2]), "+f"(d[3])
        : "r"(a[0]), "r"(a[1]), "r"(a[2]), "r"(a[3]), "r"(b0), "r"(b1));
}

// ---------------------------------------------------------------------------
// tf32 tensor-core 32-row GEMM: N-tile 128, 128 threads (4 warps).
// W fp32 streamed via 3-stage cp.async pipeline, consumed directly by LDS.
// X converted to tf32 once per block. KPER must be 160 (10 chunks of 16).
// ---------------------------------------------------------------------------
template <int KPER, int NCOLS, int XSTRIDE>
__device__ __forceinline__
void gemm32_tf(const float* __restrict__ Xp, const float* __restrict__ W,
               float* __restrict__ part, int n0, int kbase, int ksIdx) {
    __shared__ __align__(16) float    Wfs[3][16][136];   // 26.1 KB
    __shared__ __align__(16) uint32_t Xs[32][164];       // 21.0 KB (tf32 bits)

    const int t    = threadIdx.x;
    const int lane = t & 31;
    const int warp = t >> 5;
    const int g = lane >> 2;        // 0..7
    const int q = lane & 3;         // 0..3
    constexpr int NCH = KPER / 16;  // 10

    float d[2][4][4];
#pragma unroll
    for (int m = 0; m < 2; m++)
#pragma unroll
        for (int s = 0; s < 4; s++)
#pragma unroll
            for (int u = 0; u < 4; u++) d[m][s][u] = 0.0f;

    // ---- prologue: commit W chunks 0 and 1; stage + convert whole X slice
    auto issue_w = [&](int c) {
        const int kg = kbase + c * 16;
        const int buf = c % 3;
#pragma unroll
        for (int r = 0; r < 4; r++) {
            int s = t + r * 128, k = s >> 5, seg = s & 31;
            cp_async16(smem_u32(&Wfs[buf][k][seg * 4]),
                       &W[(size_t)(kg + k) * NCOLS + n0 + seg * 4]);
        }
        CP_COMMIT();
    };
    issue_w(0);
    if (NCH > 1) issue_w(1);

#pragma unroll
    for (int r = 0; r < KPER / 16; r++) {
        int i = t + r * 128;
        int b = i / (KPER / 4), c4 = i % (KPER / 4);
        float4 v = *reinterpret_cast<const float4*>(
            &Xp[(size_t)b * XSTRIDE + kbase + c4 * 4]);
        uint4 u = make_uint4(f2tf(v.x), f2tf(v.y), f2tf(v.z), f2tf(v.w));
        *reinterpret_cast<uint4*>(&Xs[b][c4 * 4]) = u;
    }

    for (int c = 0; c < NCH; c++) {
        if (c + 1 < NCH) { CP_WAIT(1); } else { CP_WAIT(0); }
        __syncthreads();                 // chunk c visible; prev compute done
        if (c + 2 < NCH) issue_w(c + 2); // into buffer freed at this sync
        const int buf = c % 3;
        const int kk0 = c * 16;
#pragma unroll
        for (int s = 0; s < 2; s++) {    // two k8 steps
            const int kA = kk0 + s * 8;
            uint32_t a0[4], a1[4];
            a0[0] = Xs[g][kA + q];
            a0[1] = Xs[g + 8][kA + q];
            a0[2] = Xs[g][kA + q + 4];
            a0[3] = Xs[g + 8][kA + q + 4];
            a1[0] = Xs[16 + g][kA + q];
            a1[1] = Xs[24 + g][kA + q];
            a1[2] = Xs[16 + g][kA + q + 4];
            a1[3] = Xs[24 + g][kA + q + 4];
#pragma unroll
            for (int nt = 0; nt < 4; nt++) {
                const int col = warp * 32 + nt * 8 + g;
                uint32_t b0 = f2tf(Wfs[buf][s * 8 + q][col]);
                uint32_t b1 = f2tf(Wfs[buf][s * 8 + q + 4][col]);
                mma_tf32(d[0][nt], a0, b0, b1);
                mma_tf32(d[1][nt], a1, b0, b1);
            }
        }
        __syncthreads();                 // done with Wfs[buf] before overwrite
    }

    // epilogue
#pragma unroll
    for (int mt = 0; mt < 2; mt++) {
#pragma unroll
        for (int s = 0; s < 4; s++) {
            int col = n0 + warp * 32 + s * 8 + q * 2;
            size_t r0 = (size_t)(ksIdx * Bm + mt * 16 + g) * NCOLS + col;
            size_t r1 = (size_t)(ksIdx * Bm + mt * 16 + g + 8) * NCOLS + col;
            *reinterpret_cast<float2*>(&part[r0]) =
                make_float2(d[mt][s][0], d[mt][s][1]);
            *reinterpret_cast<float2*>(&part[r1]) =
                make_float2(d[mt][s][2], d[mt][s][3]);
        }
    }
}

__global__ __launch_bounds__(128)
void gemm_ssm_kernel(const float* __restrict__ X, const float* __restrict__ W) {
    constexpr int KPER = Dm / KS_IN;  // 160
    gemm32_tf<KPER, Em, Dm>(X, W, g_p_ssm, blockIdx.x * 128,
                            blockIdx.y * KPER, blockIdx.y);
}
__global__ __launch_bounds__(128)
void gemm_mlp_kernel(const float* __restrict__ X, const float* __restrict__ W) {
    constexpr int KPER = Dm / KS_IN;  // 160
    gemm32_tf<KPER, Em, Dm>(X, W, g_p_mlp, blockIdx.x * 128,
                            blockIdx.y * KPER, blockIdx.y);
}
__global__ __launch_bounds__(128)
void gemm_out_kernel(const float* __restrict__ W) {
    constexpr int KPER = Em / KS_OUT;  // 160
    gemm32_tf<KPER, Dm, Em>(g_z, W, g_p_out, blockIdx.x * 128,
                            blockIdx.y * KPER, blockIdx.y);
}

// ---------------------------------------------------------------------------
// dbc GEMM (R6-proven): xt(32,5120) @ Wx(5120,192), f32x2 pipelined.
// ---------------------------------------------------------------------------
__global__ __launch_bounds__(128)
void dbc_gemm_kernel(const float* __restrict__ Wx) {
    __shared__ ull Wsb[2][32][32];
    __shared__ ull Xsb[2][32][33];

    const int t  = threadIdx.x;
    const int n0 = blockIdx.x * 64;
    constexpr int KPER = Em / KS_DBC;  // 128
    constexpr int NCH  = KPER / 32;    // 4
    const int kbase = blockIdx.y * KPER;
    const int cg = t & 15;
    const int rg = t >> 4;
    const int b0 = rg * 4;
    const int qu = cg * 2;

    ull acc[4][2];
#pragma unroll
    for (int j = 0; j < 4; j++) { acc[j][0] = 0ULL; acc[j][1] = 0ULL; }

    float xreg[8];
    {
        const int kg = kbase;
#pragma unroll
        for (int r = 0; r < 4; r++) {
            int s = t + r * 128, row = s >> 4, c16 = s & 15;
            cp_async16(smem_u32(&Wsb[0][row][c16 * 2]),
                       &Wx[(size_t)(kg + row) * 192 + n0 + c16 * 4]);
        }
        CP_COMMIT();
#pragma unroll
        for (int r = 0; r < 8; r++) {
            int i = t + r * 128, b = i >> 5, kk = i & 31;
            xreg[r] = g_xt[b * Em + kg + kk];
        }
    }

    for (int c = 0; c < NCH; c++) {
        const int p = c & 1;
#pragma unroll
        for (int r = 0; r < 8; r++) {
            int i = t + r * 128, b = i >> 5, kk = i & 31;
            Xsb[p][kk][b] = pack2(xreg[r], xreg[r]);
        }
        if (c + 1 < NCH) {
            const int kg = kbase + (c + 1) * 32;
#pragma unroll
            for (int r = 0; r < 4; r++) {
                int s = t + r * 128, row = s >> 4, c16 = s & 15;
                cp_async16(smem_u32(&Wsb[1 - p][row][c16 * 2]),
                           &Wx[(size_t)(kg + row) * 192 + n0 + c16 * 4]);
            }
            CP_COMMIT();
#pragma unroll
            for (int r = 0; r < 8; r++) {
                int i = t + r * 128, b = i >> 5, kk = i & 31;
                xreg[r] = g_xt[b * Em + kg + kk];
            }
            CP_WAIT(1);
        } else {
            CP_WAIT(0);
        }
        __syncthreads();
#pragma unroll
        for (int kk = 0; kk < 32; kk++) {
            ulonglong2 w = *reinterpret_cast<const ulonglong2*>(&Wsb[p][kk][qu]);
            ull xs[4] = {Xsb[p][kk][b0], Xsb[p][kk][b0 + 1],
                         Xsb[p][kk][b0 + 2], Xsb[p][kk][b0 + 3]};
#pragma unroll
            for (int j = 0; j < 4; j++) {
                fma2(acc[j][0], xs[j], w.x);
                fma2(acc[j][1], xs[j], w.y);
            }
        }
        __syncthreads();
    }
#pragma unroll
    for (int j = 0; j < 4; j++) {
        float2 a0 = unpack2(acc[j][0]);
        float2 a1 = unpack2(acc[j][1]);
        *reinterpret_cast<float4*>(
            &g_dbcp[((size_t)blockIdx.y * Bm + b0 + j) * 192 + n0 + cg * 4]) =
            make_float4(a0.x, a0.y, a1.x, a1.y);
    }
}

// ---------------------------------------------------------------------------
__global__ __launch_bounds__(256)
void conv_silu_kernel(const float* __restrict__ conv_w,
                      const float* __restrict__ conv_b,
                      const float* __restrict__ conv_states) {
    int idx = blockIdx.x * 256 + threadIdx.x;
    float xssm = 0.0f, xmlp = 0.0f;
#pragma unroll
    for (int ks = 0; ks < KS_IN; ks++) {
        xssm += g_p_ssm[idx + ks * BE];
        xmlp += g_p_mlp[idx + ks * BE];
    }
    float c = conv_b[idx];
    c += conv_states[idx]          * conv_w[idx];
    c += conv_states[idx + BE]     * conv_w[idx + BE];
    c += conv_states[idx + 2 * BE] * conv_w[idx + 2 * BE];
    c += xssm                      * conv_w[idx + 3 * BE];
    g_xt[idx]  = silu_f(c);
    g_res[idx] = silu_f(xmlp);
}

__global__ void dbc_reduce_kernel() {
    int i = blockIdx.x * 256 + threadIdx.x;  // [0, 6144)
    float s = 0.0f;
#pragma unroll 8
    for (int ks = 0; ks < KS_DBC; ks++) s += g_dbcp[ks * Bm * 192 + i];
    g_dbc[i] = s;
}

// ---------------------------------------------------------------------------
__global__ __launch_bounds__(256)
void ssm_kernel(const float* __restrict__ W_dt,
                const float* __restrict__ dt_bias,
                const float* __restrict__ A_log,
                const float* __restrict__ Dv,
                const float* __restrict__ h) {
    int gid = blockIdx.x * 256 + threadIdx.x;  // [0, 16*Em)
    int e  = gid % Em;
    int b0 = (gid / Em) * 2;

    float dt0 = 0.0f, dt1 = 0.0f;
#pragma unroll 8
    for (int k = 0; k < RK; k++) {
        float wd = W_dt[(size_t)k * Em + e];
        dt0 += g_dbc[b0 * 192 + k] * wd;
        dt1 += g_dbc[(b0 + 1) * 192 + k] * wd;
    }

    float bias = dt_bias[e];
    float dval = Dv[e];
    float An[STn];
#pragma unroll
    for (int n = 0; n < STn; n++) An[n] = -expf(A_log[(size_t)e * STn + n]);

    float dts[2] = {dt0, dt1};
#pragma unroll
    for (int j = 0; j < 2; j++) {
        int b = b0 + j;
        float s = dts[j] + bias;
        float dt = (s > 20.0f) ? s : log1pf(expf(s));
        float xt = g_xt[b * Em + e];
        const float* hb = &h[((size_t)b * Em + e) * STn];
        float y = 0.0f;
#pragma unroll
        for (int n = 0; n < STn; n++) {
            float Bv = g_dbc[b * 192 + 160 + n];
            float Cv = g_dbc[b * 192 + 176 + n];
            float dA = expf(dt * An[n]);
            float hn = hb[n] * dA + dt * Bv * xt;
            y += hn * Cv;
        }
        y += dval * xt;
        g_z[b * Em + e] = y * g_res[b * Em + e];
    }
}

__global__ void out_reduce_kernel(float* __restrict__ out) {
    int i = blockIdx.x * 256 + threadIdx.x;  // [0, BD)
    float s = 0.0f;
#pragma unroll 8
    for (int ks = 0; ks < KS_OUT; ks++) s += g_p_out[ks * BD + i];
    out[i] = s;
}

// ---------------------------------------------------------------------------
extern "C" void kernel_launch(void* const* d_in, const int* in_sizes, int n_in,
                              void* d_out, int out_size) {
    const float* x        = (const float*)d_in[0];
    const float* W_in_ssm = (const float*)d_in[1];
    const float* W_in_mlp = (const float*)d_in[2];
    const float* W_out    = (const float*)d_in[3];
    const float* conv_w   = (const float*)d_in[4];
    const float* conv_b   = (const float*)d_in[5];
    const float* conv_st  = (const float*)d_in[6];
    const float* Wx       = (const float*)d_in[7];
    const float* W_dt     = (const float*)d_in[8];
    const float* dt_bias  = (const float*)d_in[9];
    const float* A_log    = (const float*)d_in[10];
    const float* Dvec     = (const float*)d_in[11];
    const float* h        = (const float*)d_in[12];
    float* out = (float*)d_out;

    gemm_ssm_kernel<<<dim3(40, KS_IN), 128>>>(x, W_in_ssm);
    gemm_mlp_kernel<<<dim3(40, KS_IN), 128>>>(x, W_in_mlp);
    conv_silu_kernel<<<BE / 256, 256>>>(conv_w, conv_b, conv_st);
    dbc_gemm_kernel<<<dim3(3, KS_DBC), 128>>>(Wx);
    dbc_reduce_kernel<<<24, 256>>>();
    ssm_kernel<<<320, 256>>>(W_dt, dt_bias, A_log, Dvec, h);
    gemm_out_kernel<<<dim3(20, KS_OUT), 128>>>(W_out);
    out_reduce_kernel<<<BD / 256, 256>>>(out);
}

// round 9
// speedup vs baseline: 2.7402x; 1.0695x over previous
#include <cuda_runtime.h>
#include <cuda_bf16.h>
#include <cstdint>

#define Bm   32
#define Dm   2560
#define Em   5120
#define RK   160
#define STn  16
#define BE   (Bm*Em)
#define BD   (Bm*Dm)
#define KS_IN   8
#define KS_OUT  16
#define KS_DBC  40

typedef unsigned long long ull;

// -------- scratch ----------
__device__ float g_p_ssm[KS_IN * BE];
__device__ float g_p_mlp[KS_IN * BE];
__device__ float g_xt   [BE];
__device__ float g_res  [BE];
__device__ float g_dbcp [KS_DBC * Bm * 192];
__device__ float g_dbc  [Bm * 192];
__device__ float g_z    [BE];
__device__ float g_p_out[KS_OUT * BD];

// -------- helpers ----------
__device__ __forceinline__ ull pack2(float x, float y) {
    ull r;
    asm("mov.b64 %0, {%1,%2};" : "=l"(r) : "f"(x), "f"(y));
    return r;
}
__device__ __forceinline__ void fma2(ull& d, ull a, ull b) {
    asm("fma.rn.f32x2 %0, %1, %2, %0;" : "+l"(d) : "l"(a), "l"(b));
}
__device__ __forceinline__ float2 unpack2(ull v) {
    float2 r;
    asm("mov.b64 {%0,%1}, %2;" : "=f"(r.x), "=f"(r.y) : "l"(v));
    return r;
}
__device__ __forceinline__ float silu_f(float v) {
    return v * (1.0f / (1.0f + expf(-v)));
}
__device__ __forceinline__ uint32_t smem_u32(const void* p) {
    uint32_t a;
    asm("{ .reg .u64 t; cvta.to.shared.u64 t, %1; cvt.u32.u64 %0, t; }"
        : "=r"(a) : "l"(p));
    return a;
}
__device__ __forceinline__ void cp_async16(uint32_t dst, const void* src) {
    asm volatile("cp.async.cg.shared.global [%0], [%1], 16;"
                 :: "r"(dst), "l"(src));
}
#define CP_COMMIT()  asm volatile("cp.async.commit_group;")
#define CP_WAIT(n)   asm volatile("cp.async.wait_group %0;" :: "n"(n))

__device__ __forceinline__ uint32_t f2tf(float v) {
    uint32_t u;
    asm("cvt.rna.tf32.f32 %0, %1;" : "=r"(u) : "f"(v));
    return u;
}
__device__ __forceinline__ void mma_tf32(float* d, const uint32_t* a,
                                         uint32_t b0, uint32_t b1) {
    asm volatile(
        "mma.sync.aligned.m16n8k8.row.col.f32.tf32.tf32.f32 "
        "{%0,%1,%2,%3}, {%4,%5,%6,%7}, {%8,%9}, {%0,%1,%2,%3};"
        : "+f"(d[0]), "+f"(d[1]), "+f"(d[2]), "+f"(d[3])
        : "r"(a[0]), "r"(a[1]), "r"(a[2]), "r"(a[3]), "r"(b0), "r"(b1));
}

// ---------------------------------------------------------------------------
// tf32 tensor-core 32-row GEMM: N-tile 128, 128 threads (4 warps).
// W: 3-stage cp.async pipeline, ONE __syncthreads per chunk.
// X: per-chunk tf32 double buffer, LDG prefetched one chunk ahead.
// ---------------------------------------------------------------------------
template <int KPER, int NCOLS, int XSTRIDE>
__device__ __forceinline__
void gemm32_tf2(const float* __restrict__ Xp, const float* __restrict__ W,
                float* __restrict__ part, int n0, int kbase, int ksIdx) {
    __shared__ __align__(16) float    Wfs[3][16][136];   // 26.1 KB
    __shared__ __align__(16) uint32_t Xs[2][32][20];     // 5.1 KB

    const int t    = threadIdx.x;
    const int lane = t & 31;
    const int warp = t >> 5;
    const int g = lane >> 2;
    const int q = lane & 3;
    constexpr int NCH = KPER / 16;   // 20

    float d[2][4][4];
#pragma unroll
    for (int m = 0; m < 2; m++)
#pragma unroll
        for (int s = 0; s < 4; s++)
#pragma unroll
            for (int u = 0; u < 4; u++) d[m][s][u] = 0.0f;

    auto issue_w = [&](int c) {
        const int kg = kbase + c * 16;
        const int buf = c % 3;
#pragma unroll
        for (int r = 0; r < 4; r++) {
            int s = t + r * 128, k = s >> 5, seg = s & 31;
            cp_async16(smem_u32(&Wfs[buf][k][seg * 4]),
                       &W[(size_t)(kg + k) * NCOLS + n0 + seg * 4]);
        }
        CP_COMMIT();
    };

    float xreg[4];
    auto load_x = [&](int c) {
        const int kg = kbase + c * 16;
#pragma unroll
        for (int r = 0; r < 4; r++) {
            int i = t + r * 128, b = i >> 4, k = i & 15;
            xreg[r] = Xp[(size_t)b * XSTRIDE + kg + k];
        }
    };
    auto store_x = [&](int c) {
        uint32_t* dst = &Xs[c & 1][0][0];
#pragma unroll
        for (int r = 0; r < 4; r++) {
            int i = t + r * 128, b = i >> 4, k = i & 15;
            dst[b * 20 + k] = f2tf(xreg[r]);
        }
    };

    // prologue: W chunks 0,1 in flight; X chunk 0 staged; X chunk 1 in regs
    issue_w(0);
    if (NCH > 1) issue_w(1);
    load_x(0);
    store_x(0);
    if (NCH > 1) load_x(1);

    for (int c = 0; c < NCH; c++) {
        if (c + 1 < NCH) { CP_WAIT(1); } else { CP_WAIT(0); }
        __syncthreads();   // W chunk c + Xs[c&1] ready; all done with c-1
        if (c + 2 < NCH) issue_w(c + 2);
        if (c + 1 < NCH) store_x(c + 1);   // buffer (c+1)&1 freed at sync
        if (c + 2 < NCH) load_x(c + 2);    // LDG in flight during compute

        const int buf = c % 3;
        const uint32_t* Xc = &Xs[c & 1][0][0];
#pragma unroll
        for (int s = 0; s < 2; s++) {      // two k8 steps
            const int kA = s * 8;
            uint32_t a0[4], a1[4];
            a0[0] = Xc[g * 20 + kA + q];
            a0[1] = Xc[(g + 8) * 20 + kA + q];
            a0[2] = Xc[g * 20 + kA + q + 4];
            a0[3] = Xc[(g + 8) * 20 + kA + q + 4];
            a1[0] = Xc[(16 + g) * 20 + kA + q];
            a1[1] = Xc[(24 + g) * 20 + kA + q];
            a1[2] = Xc[(16 + g) * 20 + kA + q + 4];
            a1[3] = Xc[(24 + g) * 20 + kA + q + 4];
#pragma unroll
            for (int nt = 0; nt < 4; nt++) {
                const int col = warp * 32 + nt * 8 + g;
                uint32_t b0 = f2tf(Wfs[buf][s * 8 + q][col]);
                uint32_t b1 = f2tf(Wfs[buf][s * 8 + q + 4][col]);
                mma_tf32(d[0][nt], a0, b0, b1);
                mma_tf32(d[1][nt], a1, b0, b1);
            }
        }
    }

    // epilogue
#pragma unroll
    for (int mt = 0; mt < 2; mt++) {
#pragma unroll
        for (int s = 0; s < 4; s++) {
            int col = n0 + warp * 32 + s * 8 + q * 2;
            size_t r0 = (size_t)(ksIdx * Bm + mt * 16 + g) * NCOLS + col;
            size_t r1 = (size_t)(ksIdx * Bm + mt * 16 + g + 8) * NCOLS + col;
            *reinterpret_cast<float2*>(&part[r0]) =
                make_float2(d[mt][s][0], d[mt][s][1]);
            *reinterpret_cast<float2*>(&part[r1]) =
                make_float2(d[mt][s][2], d[mt][s][3]);
        }
    }
}

// Fused input GEMMs: blockIdx.z selects ssm / mlp. grid(40, KS_IN, 2).
__global__ __launch_bounds__(128)
void gemm_in_kernel(const float* __restrict__ X,
                    const float* __restrict__ W0,
                    const float* __restrict__ W1) {
    const float* W = (blockIdx.z == 0) ? W0 : W1;
    float* part    = (blockIdx.z == 0) ? g_p_ssm : g_p_mlp;
    constexpr int KPER = Dm / KS_IN;  // 320
    gemm32_tf2<KPER, Em, Dm>(X, W, part, blockIdx.x * 128,
                             blockIdx.y * KPER, blockIdx.y);
}
__global__ __launch_bounds__(128)
void gemm_out_kernel(const float* __restrict__ W) {
    constexpr int KPER = Em / KS_OUT;  // 320
    gemm32_tf2<KPER, Dm, Em>(g_z, W, g_p_out, blockIdx.x * 128,
                             blockIdx.y * KPER, blockIdx.y);
}

// ---------------------------------------------------------------------------
// dbc GEMM (R6-proven): xt(32,5120) @ Wx(5120,192), f32x2 pipelined.
// ---------------------------------------------------------------------------
__global__ __launch_bounds__(128)
void dbc_gemm_kernel(const float* __restrict__ Wx) {
    __shared__ ull Wsb[2][32][32];
    __shared__ ull Xsb[2][32][33];

    const int t  = threadIdx.x;
    const int n0 = blockIdx.x * 64;
    constexpr int KPER = Em / KS_DBC;  // 128
    constexpr int NCH  = KPER / 32;    // 4
    const int kbase = blockIdx.y * KPER;
    const int cg = t & 15;
    const int rg = t >> 4;
    const int b0 = rg * 4;
    const int qu = cg * 2;

    ull acc[4][2];
#pragma unroll
    for (int j = 0; j < 4; j++) { acc[j][0] = 0ULL; acc[j][1] = 0ULL; }

    float xreg[8];
    {
        const int kg = kbase;
#pragma unroll
        for (int r = 0; r < 4; r++) {
            int s = t + r * 128, row = s >> 4, c16 = s & 15;
            cp_async16(smem_u32(&Wsb[0][row][c16 * 2]),
                       &Wx[(size_t)(kg + row) * 192 + n0 + c16 * 4]);
        }
        CP_COMMIT();
#pragma unroll
        for (int r = 0; r < 8; r++) {
            int i = t + r * 128, b = i >> 5, kk = i & 31;
            xreg[r] = g_xt[b * Em + kg + kk];
        }
    }

    for (int c = 0; c < NCH; c++) {
        const int p = c & 1;
#pragma unroll
        for (int r = 0; r < 8; r++) {
            int i = t + r * 128, b = i >> 5, kk = i & 31;
            Xsb[p][kk][b] = pack2(xreg[r], xreg[r]);
        }
        if (c + 1 < NCH) {
            const int kg = kbase + (c + 1) * 32;
#pragma unroll
            for (int r = 0; r < 4; r++) {
                int s = t + r * 128, row = s >> 4, c16 = s & 15;
                cp_async16(smem_u32(&Wsb[1 - p][row][c16 * 2]),
                           &Wx[(size_t)(kg + row) * 192 + n0 + c16 * 4]);
            }
            CP_COMMIT();
#pragma unroll
            for (int r = 0; r < 8; r++) {
                int i = t + r * 128, b = i >> 5, kk = i & 31;
                xreg[r] = g_xt[b * Em + kg + kk];
            }
            CP_WAIT(1);
        } else {
            CP_WAIT(0);
        }
        __syncthreads();
#pragma unroll
        for (int kk = 0; kk < 32; kk++) {
            ulonglong2 w = *reinterpret_cast<const ulonglong2*>(&Wsb[p][kk][qu]);
            ull xs[4] = {Xsb[p][kk][b0], Xsb[p][kk][b0 + 1],
                         Xsb[p][kk][b0 + 2], Xsb[p][kk][b0 + 3]};
#pragma unroll
            for (int j = 0; j < 4; j++) {
                fma2(acc[j][0], xs[j], w.x);
                fma2(acc[j][1], xs[j], w.y);
            }
        }
        __syncthreads();
    }
#pragma unroll
    for (int j = 0; j < 4; j++) {
        float2 a0 = unpack2(acc[j][0]);
        float2 a1 = unpack2(acc[j][1]);
        *reinterpret_cast<float4*>(
            &g_dbcp[((size_t)blockIdx.y * Bm + b0 + j) * 192 + n0 + cg * 4]) =
            make_float4(a0.x, a0.y, a1.x, a1.y);
    }
}

// ---------------------------------------------------------------------------
__global__ __launch_bounds__(256)
void conv_silu_kernel(const float* __restrict__ conv_w,
                      const float* __restrict__ conv_b,
                      const float* __restrict__ conv_states) {
    int idx = blockIdx.x * 256 + threadIdx.x;
    float xssm = 0.0f, xmlp = 0.0f;
#pragma unroll
    for (int ks = 0; ks < KS_IN; ks++) {
        xssm += g_p_ssm[idx + ks * BE];
        xmlp += g_p_mlp[idx + ks * BE];
    }
    float c = conv_b[idx];
    c += conv_states[idx]          * conv_w[idx];
    c += conv_states[idx + BE]     * conv_w[idx + BE];
    c += conv_states[idx + 2 * BE] * conv_w[idx + 2 * BE];
    c += xssm                      * conv_w[idx + 3 * BE];
    g_xt[idx]  = silu_f(c);
    g_res[idx] = silu_f(xmlp);
}

__global__ void dbc_reduce_kernel() {
    int i = blockIdx.x * 256 + threadIdx.x;  // [0, 6144)
    float s = 0.0f;
#pragma unroll 8
    for (int ks = 0; ks < KS_DBC; ks++) s += g_dbcp[ks * Bm * 192 + i];
    g_dbc[i] = s;
}

// ---------------------------------------------------------------------------
__global__ __launch_bounds__(256)
void ssm_kernel(const float* __restrict__ W_dt,
                const float* __restrict__ dt_bias,
                const float* __restrict__ A_log,
                const float* __restrict__ Dv,
                const float* __restrict__ h) {
    int gid = blockIdx.x * 256 + threadIdx.x;  // [0, 16*Em)
    int e  = gid % Em;
    int b0 = (gid / Em) * 2;

    float dt0 = 0.0f, dt1 = 0.0f;
#pragma unroll 8
    for (int k = 0; k < RK; k++) {
        float wd = W_dt[(size_t)k * Em + e];
        dt0 += g_dbc[b0 * 192 + k] * wd;
        dt1 += g_dbc[(b0 + 1) * 192 + k] * wd;
    }

    float bias = dt_bias[e];
    float dval = Dv[e];
    float An[STn];
#pragma unroll
    for (int n = 0; n < STn; n++) An[n] = -expf(A_log[(size_t)e * STn + n]);

    float dts[2] = {dt0, dt1};
#pragma unroll
    for (int j = 0; j < 2; j++) {
        int b = b0 + j;
        float s = dts[j] + bias;
        float dt = (s > 20.0f) ? s : log1pf(expf(s));
        float xt = g_xt[b * Em + e];
        const float* hb = &h[((size_t)b * Em + e) * STn];
        float y = 0.0f;
#pragma unroll
        for (int n = 0; n < STn; n++) {
            float Bv = g_dbc[b * 192 + 160 + n];
            float Cv = g_dbc[b * 192 + 176 + n];
            float dA = expf(dt * An[n]);
            float hn = hb[n] * dA + dt * Bv * xt;
            y += hn * Cv;
        }
        y += dval * xt;
        g_z[b * Em + e] = y * g_res[b * Em + e];
    }
}

__global__ void out_reduce_kernel(float* __restrict__ out) {
    int i = blockIdx.x * 256 + threadIdx.x;  // [0, BD)
    float s = 0.0f;
#pragma unroll 8
    for (int ks = 0; ks < KS_OUT; ks++) s += g_p_out[ks * BD + i];
    out[i] = s;
}

// ---------------------------------------------------------------------------
extern "C" void kernel_launch(void* const* d_in, const int* in_sizes, int n_in,
                              void* d_out, int out_size) {
    const float* x        = (const float*)d_in[0];
    const float* W_in_ssm = (const float*)d_in[1];
    const float* W_in_mlp = (const float*)d_in[2];
    const float* W_out    = (const float*)d_in[3];
    const float* conv_w   = (const float*)d_in[4];
    const float* conv_b   = (const float*)d_in[5];
    const float* conv_st  = (const float*)d_in[6];
    const float* Wx       = (const float*)d_in[7];
    const float* W_dt     = (const float*)d_in[8];
    const float* dt_bias  = (const float*)d_in[9];
    const float* A_log    = (const float*)d_in[10];
    const float* Dvec     = (const float*)d_in[11];
    const float* h        = (const float*)d_in[12];
    float* out = (float*)d_out;

    gemm_in_kernel<<<dim3(40, KS_IN, 2), 128>>>(x, W_in_ssm, W_in_mlp);
    conv_silu_kernel<<<BE / 256, 256>>>(conv_w, conv_b, conv_st);
    dbc_gemm_kernel<<<dim3(3, KS_DBC), 128>>>(Wx);
    dbc_reduce_kernel<<<24, 256>>>();
    ssm_kernel<<<320, 256>>>(W_dt, dt_bias, A_log, Dvec, h);
    gemm_out_kernel<<<dim3(20, KS_OUT), 128>>>(W_out);
    out_reduce_kernel<<<BD / 256, 256>>>(out);
}